// round 11
// baseline (speedup 1.0000x reference)
#include <cuda_runtime.h>
#include <cstdint>

typedef unsigned long long u64;

#define NB 8
#define WD 96
#define HD 96
#define CD 256
#define PBATCH (WD*HD)            /* 9216 */
#define BOFF (PBATCH*CD)          /* 2359296 floats per batch */
#define ARRN (NB*BOFF)            /* 18874368 */
#define NSPLIT 48
#define KSPLIT 512

// ---------------- device scratch ----------------
__device__ float g_z[ARRN];                   // z = G x, layout [b][w][h][c] (p-major)
__device__ float g_v[ARRN];                   // v, layout [b][w][h][c] (p-major)
__device__ float g_Sp[NSPLIT * 16 * PBATCH];  // [split][mode*8+b][96][96]
__device__ float g_P[16 * PBATCH];            // softmaxed probs
__device__ float g_wc[512 * 256];             // [G ; Wv] combined weight
__device__ float g_u[256];                    // Wq^T bk
__device__ float g_u2[256];                   // Wk^T bq
__device__ float g_corr[2 * 768];             // [Cms ; Cma] col corrections

// ---------------- f32x2 helpers ----------------
__device__ __forceinline__ void ffma2(u64 &d, u64 a, u64 b) {
    asm("fma.rn.f32x2 %0, %1, %2, %0;" : "+l"(d) : "l"(a), "l"(b));
}
__device__ __forceinline__ u64 dup2(float x) {
    u64 r; asm("mov.b64 %0, {%1, %1};" : "=l"(r) : "f"(x)); return r;
}
__device__ __forceinline__ float2 unpack2(u64 v) {
    float2 f; asm("mov.b64 {%0, %1}, %2;" : "=f"(f.x), "=f"(f.y) : "l"(v)); return f;
}
// 16B of data -> two 8B smem stores (dst may be only 8B-aligned)
__device__ __forceinline__ void st_f4_2x(float* p, float4 v) {
    *(float2*)p       = make_float2(v.x, v.y);
    *(float2*)(p + 2) = make_float2(v.z, v.w);
}

// ============================================================================
// Kernel 0: prep. Blocks 0..255: G[o][c] = sum_t Wq[t][o]*Wk[t][c].
// Blocks 256..511: copy Wv rows. Block 512: u. Block 513: u2.
// ============================================================================
__global__ __launch_bounds__(256) void prep_kernel(
    const float* __restrict__ W, const float* __restrict__ bias)
{
    const int blk = blockIdx.x;
    const int c = threadIdx.x;
    if (blk < 256) {
        __shared__ float sWq[256];
        sWq[c] = W[c * 256 + blk];          // Wq[t=c][o=blk]
        __syncthreads();
        float acc = 0.f;
#pragma unroll 4
        for (int t = 0; t < 256; t++)
            acc += sWq[t] * W[(256 + t) * 256 + c];   // Wk[t][c]
        g_wc[blk * 256 + c] = acc;          // G[o=blk][c]
    } else if (blk < 512) {
        int o = blk - 256;
        g_wc[(256 + o) * 256 + c] = W[(512 + o) * 256 + c];   // Wv[o][c]
    } else if (blk == 512) {
        float acc = 0.f;
#pragma unroll 4
        for (int t = 0; t < 256; t++)
            acc += W[t * 256 + c] * bias[256 + t];    // Wq[t][c]*bk[t]
        g_u[c] = acc;
    } else {
        float acc = 0.f;
#pragma unroll 4
        for (int t = 0; t < 256; t++)
            acc += W[(256 + t) * 256 + c] * bias[t];  // Wk[t][c]*bq[t]
        g_u2[c] = acc;
    }
}

// ============================================================================
// Kernel 1: main GEMM, k-paired f32x2. Y[p][o] = sum_c X[p][c]*Wcomb[o][c]
// M=73728, N=512, K=256. Tile 128x64, BK=16, 256 threads, 8x4 microtile where
// each acc is an f32x2 pair over adjacent k (horizontal-summed at the end).
// Strides 18 (== 2 mod 32 -> conflict-free LDS.64 B reads); smem staging via
// 8B stores (16B stores would be misaligned on odd rows).
// ============================================================================
#define GA_STR 18                 /* k stride 16 + pad 2 */
#define GA_SZ  (128 * GA_STR)
#define GB_SZ  (64 * GA_STR)

__global__ __launch_bounds__(256, 2) void gemm_kernel(
    const float* __restrict__ X, const float* __restrict__ bias)
{
    __shared__ __align__(16) float As[2][GA_SZ];   // [row][k]
    __shared__ __align__(16) float Bs[2][GB_SZ];   // [col][k]

    const int tid = threadIdx.x;
    const int tx = tid & 15, ty = tid >> 4;
    const int m0 = blockIdx.x * 128;
    const int n0 = blockIdx.y * 64;

    const float* Ag = X    + (size_t)m0 * CD;
    const float* Bg = g_wc + (size_t)n0 * CD;

    const int rowA = tid >> 2;    // 0..63 (+64)
    const int q4   = tid & 3;

    u64 acc[8][4];
#pragma unroll
    for (int i = 0; i < 8; i++)
#pragma unroll
        for (int j = 0; j < 4; j++) acc[i][j] = 0ULL;

    float4 ra[2], rb;
    ra[0] = *(const float4*)(Ag + (size_t)rowA * CD + q4 * 4);
    ra[1] = *(const float4*)(Ag + (size_t)(rowA + 64) * CD + q4 * 4);
    rb    = *(const float4*)(Bg + (size_t)rowA * CD + q4 * 4);
    st_f4_2x(&As[0][rowA * GA_STR + q4 * 4],        ra[0]);
    st_f4_2x(&As[0][(rowA + 64) * GA_STR + q4 * 4], ra[1]);
    st_f4_2x(&Bs[0][rowA * GA_STR + q4 * 4],        rb);
    __syncthreads();

#pragma unroll 1
    for (int s = 0; s < 16; s++) {
        const int buf = s & 1;
        if (s < 15) {
            int ks = (s + 1) * 16;
            ra[0] = *(const float4*)(Ag + (size_t)rowA * CD + ks + q4 * 4);
            ra[1] = *(const float4*)(Ag + (size_t)(rowA + 64) * CD + ks + q4 * 4);
            rb    = *(const float4*)(Bg + (size_t)rowA * CD + ks + q4 * 4);
        }
        const float* Ab = As[buf];
        const float* Bb = Bs[buf];
#pragma unroll
        for (int k2 = 0; k2 < 8; k2++) {
            u64 a2[8], b2[4];
#pragma unroll
            for (int i = 0; i < 8; i++)
                a2[i] = *(const u64*)&Ab[(ty * 8 + i) * GA_STR + 2 * k2];
#pragma unroll
            for (int j = 0; j < 4; j++)
                b2[j] = *(const u64*)&Bb[(tx + 16 * j) * GA_STR + 2 * k2];
#pragma unroll
            for (int i = 0; i < 8; i++)
#pragma unroll
                for (int j = 0; j < 4; j++) ffma2(acc[i][j], a2[i], b2[j]);
        }
        if (s < 15) {
            const int nbuf = buf ^ 1;
            st_f4_2x(&As[nbuf][rowA * GA_STR + q4 * 4],        ra[0]);
            st_f4_2x(&As[nbuf][(rowA + 64) * GA_STR + q4 * 4], ra[1]);
            st_f4_2x(&Bs[nbuf][rowA * GA_STR + q4 * 4],        rb);
            __syncthreads();
        }
    }

    // epilogue: horizontal sum; p-major store; bias only for v half
    const int isv   = (n0 >= 256);
    const int cbase = n0 & 255;
    float* dst = isv ? g_v : g_z;
#pragma unroll
    for (int j = 0; j < 4; j++) {
        int col = tx + 16 * j;
        float bv = isv ? bias[512 + cbase + col] : 0.f;
#pragma unroll
        for (int i = 0; i < 8; i++) {
            int p = m0 + ty * 8 + i;
            float2 r = unpack2(acc[i][j]);
            dst[(size_t)p * CD + cbase + col] = r.x + r.y + bv;
        }
    }
}

// ============================================================================
// Kernel 1b: column corrections.
// ============================================================================
__global__ __launch_bounds__(256) void corr_kernel(const float* __restrict__ X)
{
    __shared__ float red[256];
    const int id = blockIdx.x;          // 0..1535
    const int which = id / 768;
    const int r = id - which * 768;
    const int b = r / 96, idx = r - b * 96;
    const int c = threadIdx.x;

    const float uv = which ? g_u[c] : g_u2[c];
    size_t base; int stride;
    if (which == 0) { base = (size_t)b * BOFF + (size_t)idx * 256; stride = 24576; }
    else           { base = (size_t)b * BOFF + (size_t)idx * 24576; stride = 256; }

    float s = 0.f;
#pragma unroll 4
    for (int t = 0; t < 96; t++)
        s += X[base + (size_t)t * stride + c];
    red[c] = s * uv;
    __syncthreads();
#pragma unroll
    for (int o = 128; o; o >>= 1) {
        if (c < o) red[c] += red[c + o];
        __syncthreads();
    }
    if (c == 0) g_corr[which * 768 + r] = red[0];
}

// ============================================================================
// Kernel 2: logit partials, k-paired f32x2. grid (NSPLIT, 16).
//  mode0 (ms): S[h,h'] = sum x_{hw}.z_{h'w}  A=x, B=z, rowStride=256,  chunkStride=24576
//  mode1 (ma): S[w,w'] = sum z_{hw}.x_{hw'}  A=z, B=x, rowStride=24576, chunkStride=256
// Both panels k-contiguous [96][34]; 6x6 microtile of f32x2 k-pairs.
// Stride 34 == 2 mod 32 -> conflict-free LDS.64 reads; 8B staging stores.
// ============================================================================
#define SA_STR 34                 /* k stride 32 + pad 2 */
#define SA_SZ  (96 * SA_STR)
#define S_SMEM (4 * SA_SZ * 4)    /* 2 arrays x 2 buffers = 52224 B */

__global__ __launch_bounds__(256, 2) void s_kernel(const float* __restrict__ X)
{
    extern __shared__ __align__(16) float ssm[];
    float* Asm = ssm;                         // [2][SA_SZ]
    float* Bsm = ssm + 2 * SA_SZ;             // [2][SA_SZ]

    const int split = blockIdx.x;
    const int mb    = blockIdx.y;
    const int mode  = mb >> 3;
    const int b     = mb & 7;

    const float* A = mode ? g_z : X;
    const float* B = mode ? X   : g_z;
    const int rowStride   = mode ? 24576 : 256;
    const int chunkStride = mode ? 256   : 24576;
    const size_t bbase = (size_t)b * BOFF;

    const int tid = threadIdx.x;
    const int tx = tid & 15, ty = tid >> 4;
    const int srow = tid >> 3;    // staging row 0..31 (+32,+64)
    const int q8   = tid & 7;

    u64 acc[6][6];
#pragma unroll
    for (int i = 0; i < 6; i++)
#pragma unroll
        for (int j = 0; j < 6; j++) acc[i][j] = 0ULL;

    float4 ra[3], rbv[3];
    {
        int kg0 = split * KSPLIT + q8 * 4;
        int chunk = kg0 >> 8, cin = kg0 & 255;
#pragma unroll
        for (int r = 0; r < 3; r++) {
            int row = srow + 32 * r;
            size_t ga = bbase + (size_t)row * rowStride + (size_t)chunk * chunkStride + cin;
            ra[r]  = *(const float4*)(A + ga);
            rbv[r] = *(const float4*)(B + ga);
        }
#pragma unroll
        for (int r = 0; r < 3; r++) {
            int row = srow + 32 * r;
            st_f4_2x(&Asm[row * SA_STR + q8 * 4], ra[r]);
            st_f4_2x(&Bsm[row * SA_STR + q8 * 4], rbv[r]);
        }
    }
    __syncthreads();

#pragma unroll 1
    for (int kb = 0; kb < KSPLIT / 32; kb++) {
        const int buf = kb & 1;
        if (kb < KSPLIT / 32 - 1) {
            int kg0 = split * KSPLIT + (kb + 1) * 32 + q8 * 4;
            int chunk = kg0 >> 8, cin = kg0 & 255;
#pragma unroll
            for (int r = 0; r < 3; r++) {
                int row = srow + 32 * r;
                size_t ga = bbase + (size_t)row * rowStride + (size_t)chunk * chunkStride + cin;
                ra[r]  = *(const float4*)(A + ga);
                rbv[r] = *(const float4*)(B + ga);
            }
        }
        const float* Ab = Asm + buf * SA_SZ;
        const float* Bb = Bsm + buf * SA_SZ;
#pragma unroll 4
        for (int k2 = 0; k2 < 16; k2++) {
            u64 a2[6], b2[6];
#pragma unroll
            for (int i = 0; i < 6; i++)
                a2[i] = *(const u64*)&Ab[(ty * 6 + i) * SA_STR + 2 * k2];
#pragma unroll
            for (int j = 0; j < 6; j++)
                b2[j] = *(const u64*)&Bb[(tx + 16 * j) * SA_STR + 2 * k2];
#pragma unroll
            for (int i = 0; i < 6; i++)
#pragma unroll
                for (int j = 0; j < 6; j++) ffma2(acc[i][j], a2[i], b2[j]);
        }
        if (kb < KSPLIT / 32 - 1) {
            const int nbuf = buf ^ 1;
#pragma unroll
            for (int r = 0; r < 3; r++) {
                int row = srow + 32 * r;
                st_f4_2x(&Asm[nbuf * SA_SZ + row * SA_STR + q8 * 4], ra[r]);
                st_f4_2x(&Bsm[nbuf * SA_SZ + row * SA_STR + q8 * 4], rbv[r]);
            }
            __syncthreads();
        }
    }

    float* dst = g_Sp + (size_t)(split * 16 + mb) * PBATCH;
#pragma unroll
    for (int i = 0; i < 6; i++)
#pragma unroll
        for (int j = 0; j < 6; j++) {
            float2 r = unpack2(acc[i][j]);
            dst[(ty * 6 + i) * 96 + tx + 16 * j] = r.x + r.y;
        }
}

// ============================================================================
// Kernel 3: softmax rows of 96 (sum NSPLIT partials + column correction).
// ============================================================================
__global__ __launch_bounds__(32) void softmax_kernel()
{
    const int rowid = blockIdx.x;
    const int mb = rowid / 96, i = rowid - mb * 96;
    const int mode = mb >> 3, b = mb & 7;
    const int t = threadIdx.x;
    const float* corr = g_corr + mode * 768 + b * 96;

    float v[3];
#pragma unroll
    for (int u = 0; u < 3; u++) {
        int j = t + 32 * u;
        float s = corr[j];
#pragma unroll
        for (int sp = 0; sp < NSPLIT; sp++)
            s += g_Sp[(size_t)(sp * 16 + mb) * PBATCH + i * 96 + j];
        v[u] = s;
    }
    float mx = fmaxf(v[0], fmaxf(v[1], v[2]));
#pragma unroll
    for (int o = 16; o; o >>= 1) mx = fmaxf(mx, __shfl_xor_sync(0xffffffffu, mx, o));
    float sum = 0.f;
#pragma unroll
    for (int u = 0; u < 3; u++) { v[u] = expf(v[u] - mx); sum += v[u]; }
#pragma unroll
    for (int o = 16; o; o >>= 1) sum += __shfl_xor_sync(0xffffffffu, sum, o);
    float inv = 1.f / sum;
#pragma unroll
    for (int u = 0; u < 3; u++)
        g_P[mb * PBATCH + i * 96 + t + 32 * u] = v[u] * inv;
}

// ============================================================================
// Kernels 4/5: O_tile(96x128) = P(96x96) * V(96x128). grid (768, 2).
// v and out both p-major [b][w][h][c]. (unchanged from 826us version)
// ============================================================================
#define PV_PS   (96 * 97)
#define PV_VS   (16 * 132)
#define PV_SMEM ((PV_PS + 2 * PV_VS) * 4)

__global__ __launch_bounds__(256, 3) void pv_kernel(float* __restrict__ out, int mode_ma)
{
    extern __shared__ __align__(16) float dsm[];
    float* Ps = dsm;
    float* Vs = dsm + PV_PS;

    const int s = blockIdx.x;
    const int ct = blockIdx.y;
    const int b = s / 96, idx = s - b * 96;
    const int c0 = ct * 128;

    size_t vbase, outBase; int vStride, outStride, pBase;
    if (mode_ma) {
        vbase   = (size_t)b * BOFF + (size_t)idx * 256;   vStride = 24576;
        outBase = (size_t)b * BOFF + (size_t)idx * 256;   outStride = 24576;
        pBase = (8 + b) * PBATCH;
    } else {
        vbase   = (size_t)b * BOFF + (size_t)idx * 24576; vStride = 256;
        outBase = (size_t)b * BOFF + (size_t)idx * 24576; outStride = 256;
        pBase = b * PBATCH;
    }

    const int tid = threadIdx.x;
    const int tx = tid & 15, ty = tid >> 4;

    for (int f = tid; f < 96 * 96; f += 256) {
        int r = f / 96, k = f - r * 96;
        Ps[r * 97 + k] = g_P[pBase + f];
    }

    const int vrow  = tid >> 5;
    const int vcolq = tid & 31;
    float4 vr[2];
#pragma unroll
    for (int r2 = 0; r2 < 2; r2++)
        vr[r2] = *(const float4*)(g_v + vbase + (size_t)(vrow + 8 * r2) * vStride + c0 + vcolq * 4);
#pragma unroll
    for (int r2 = 0; r2 < 2; r2++)
        *(float4*)&Vs[(vrow + 8 * r2) * 132 + vcolq * 4] = vr[r2];
    __syncthreads();

    u64 acc[6][4];
#pragma unroll
    for (int i = 0; i < 6; i++)
#pragma unroll
        for (int j = 0; j < 4; j++) acc[i][j] = 0ULL;

#pragma unroll 1
    for (int kb = 0; kb < 6; kb++) {
        const int buf = kb & 1;
        if (kb < 5) {
#pragma unroll
            for (int r2 = 0; r2 < 2; r2++)
                vr[r2] = *(const float4*)(g_v + vbase +
                    (size_t)((kb + 1) * 16 + vrow + 8 * r2) * vStride + c0 + vcolq * 4);
        }
        const float* Vb = Vs + buf * PV_VS;
#pragma unroll
        for (int kk = 0; kk < 16; kk++) {
            int kg = kb * 16 + kk;
            u64 a[6], bv[4];
#pragma unroll
            for (int i = 0; i < 6; i++) a[i] = dup2(Ps[(ty * 6 + i) * 97 + kg]);
#pragma unroll
            for (int j = 0; j < 4; j++) bv[j] = *(const u64*)&Vb[kk * 132 + 2 * tx + 32 * j];
#pragma unroll
            for (int i = 0; i < 6; i++)
#pragma unroll
                for (int j = 0; j < 4; j++) ffma2(acc[i][j], a[i], bv[j]);
        }
        if (kb < 5) {
            float* Vn = Vs + (buf ^ 1) * PV_VS;
#pragma unroll
            for (int r2 = 0; r2 < 2; r2++)
                *(float4*)&Vn[(vrow + 8 * r2) * 132 + vcolq * 4] = vr[r2];
            __syncthreads();
        }
    }

#pragma unroll
    for (int i = 0; i < 6; i++)
#pragma unroll
        for (int j = 0; j < 4; j++) {
            float2 r = unpack2(acc[i][j]);
            size_t addr = outBase + (size_t)(ty * 6 + i) * outStride + c0 + 2 * tx + 32 * j;
            if (mode_ma) {
                *(float2*)(out + addr) = r;
            } else {
                float2 o = *(const float2*)(out + addr);
                o.x += r.x; o.y += r.y;
                *(float2*)(out + addr) = o;
            }
        }
}

// ============================================================================
extern "C" void kernel_launch(void* const* d_in, const int* in_sizes, int n_in,
                              void* d_out, int out_size) {
    const float* x    = (const float*)d_in[0];
    const float* w    = (const float*)d_in[1];
    const float* bias = (const float*)d_in[2];
    float* out = (float*)d_out;

    static int attr_done = 0;
    if (!attr_done) {
        cudaFuncSetAttribute(pv_kernel, cudaFuncAttributeMaxDynamicSharedMemorySize, PV_SMEM);
        cudaFuncSetAttribute(s_kernel,  cudaFuncAttributeMaxDynamicSharedMemorySize, S_SMEM);
        attr_done = 1;
    }

    prep_kernel<<<514, 256>>>(w, bias);
    gemm_kernel<<<dim3(576, 8), 256>>>(x, bias);
    corr_kernel<<<1536, 256>>>(x);
    s_kernel<<<dim3(NSPLIT, 16), 256, S_SMEM>>>(x);
    softmax_kernel<<<16 * 96, 32>>>();
    pv_kernel<<<dim3(768, 2), 256, PV_SMEM>>>(out, 1);  // ma: full overwrite
    pv_kernel<<<dim3(768, 2), 256, PV_SMEM>>>(out, 0);  // ms: accumulate
}

// round 12
// speedup vs baseline: 1.0318x; 1.0318x over previous
#include <cuda_runtime.h>
#include <cstdint>

typedef unsigned long long u64;

#define NB 8
#define WD 96
#define HD 96
#define CD 256
#define PBATCH (WD*HD)            /* 9216 */
#define BOFF (PBATCH*CD)          /* 2359296 floats per batch */
#define ARRN (NB*BOFF)            /* 18874368 */
#define NSPLIT 48
#define KSPLIT 512

// ---------------- device scratch ----------------
__device__ float g_z[ARRN];                   // z = G x, layout [b][w][h][c] (p-major)
__device__ float g_v[ARRN];                   // v, layout [b][w][h][c] (p-major)
__device__ float g_Sp[NSPLIT * 16 * PBATCH];  // [split][mode*8+b][96][96]
__device__ float g_P[16 * PBATCH];            // softmaxed probs
__device__ float g_wc[512 * 256];             // [G ; Wv] combined weight
__device__ float g_u[256];                    // Wq^T bk
__device__ float g_u2[256];                   // Wk^T bq
__device__ float g_corr[2 * 768];             // [Cms ; Cma] col corrections

// ---------------- f32x2 helpers ----------------
__device__ __forceinline__ void ffma2(u64 &d, u64 a, u64 b) {
    asm("fma.rn.f32x2 %0, %1, %2, %0;" : "+l"(d) : "l"(a), "l"(b));
}
__device__ __forceinline__ float2 unpack2(u64 v) {
    float2 f; asm("mov.b64 {%0, %1}, %2;" : "=f"(f.x), "=f"(f.y) : "l"(v)); return f;
}

// ============================================================================
// Kernel 0: prep. Blocks 0..255: G[o][c] = sum_t Wq[t][o]*Wk[t][c].
// Blocks 256..511: copy Wv rows. Block 512: u. Block 513: u2.
// ============================================================================
__global__ __launch_bounds__(256) void prep_kernel(
    const float* __restrict__ W, const float* __restrict__ bias)
{
    const int blk = blockIdx.x;
    const int c = threadIdx.x;
    if (blk < 256) {
        __shared__ float sWq[256];
        sWq[c] = W[c * 256 + blk];          // Wq[t=c][o=blk]
        __syncthreads();
        float acc = 0.f;
#pragma unroll 4
        for (int t = 0; t < 256; t++)
            acc += sWq[t] * W[(256 + t) * 256 + c];   // Wk[t][c]
        g_wc[blk * 256 + c] = acc;          // G[o=blk][c]
    } else if (blk < 512) {
        int o = blk - 256;
        g_wc[(256 + o) * 256 + c] = W[(512 + o) * 256 + c];   // Wv[o][c]
    } else if (blk == 512) {
        float acc = 0.f;
#pragma unroll 4
        for (int t = 0; t < 256; t++)
            acc += W[t * 256 + c] * bias[256 + t];    // Wq[t][c]*bk[t]
        g_u[c] = acc;
    } else {
        float acc = 0.f;
#pragma unroll 4
        for (int t = 0; t < 256; t++)
            acc += W[(256 + t) * 256 + c] * bias[t];  // Wk[t][c]*bq[t]
        g_u2[c] = acc;
    }
}

// ============================================================================
// Kernel 1: main GEMM. Y[p][o] = sum_c X[p][c]*Wcomb[o][c]  (o<256 -> z, else v+bias)
// M=73728, N=512, K=256. 128x128 tile, BK=16, 256 threads, 8x8 microtile f32x2.
// A stored DUPLICATED in smem: As[k][2*row] = As[k][2*row+1] = A[row][k], so one
// LDS.64 broadcast yields the (a,a) operand pair directly (no MOV dup).
// B stored [k][col] as before. Double-buffered, one barrier per panel.
// ============================================================================
#define GA_STR 258                /* 2*128 + 2 (stride mod 32 == 2 -> <=2-way store conflicts) */
#define GA_BUF (16 * GA_STR)
#define GB_BUF (16 * 132)
#define G_SMEM ((2 * GA_BUF + 2 * GB_BUF) * 4)    /* 49920 B */

__global__ __launch_bounds__(256, 2) void gemm_kernel(
    const float* __restrict__ X, const float* __restrict__ bias)
{
    extern __shared__ __align__(16) float gsm[];
    float* As = gsm;                      // [2][GA_BUF]
    float* Bs = gsm + 2 * GA_BUF;         // [2][GB_BUF]

    const int tid = threadIdx.x;
    const int tx = tid & 15, ty = tid >> 4;
    const int m0 = blockIdx.x * 128;
    const int n0 = blockIdx.y * 128;

    const float* Ag = X    + (size_t)m0 * CD;
    const float* Bg = g_wc + (size_t)n0 * CD;

    const int rowA = tid >> 2;    // 0..63 (+64)
    const int c4   = tid & 3;

    u64 acc[8][4];
#pragma unroll
    for (int i = 0; i < 8; i++)
#pragma unroll
        for (int j = 0; j < 4; j++) acc[i][j] = 0ULL;

    float4 ra[2], rb[2];
    ra[0] = *(const float4*)(Ag + (size_t)rowA * CD + c4 * 4);
    ra[1] = *(const float4*)(Ag + (size_t)(rowA + 64) * CD + c4 * 4);
    rb[0] = *(const float4*)(Bg + (size_t)rowA * CD + c4 * 4);
    rb[1] = *(const float4*)(Bg + (size_t)(rowA + 64) * CD + c4 * 4);

    // stage panel 0 into buffer 0
    {
        const float* pa0 = (const float*)&ra[0];
        const float* pa1 = (const float*)&ra[1];
        const float* pb0 = (const float*)&rb[0];
        const float* pb1 = (const float*)&rb[1];
#pragma unroll
        for (int u = 0; u < 4; u++) {
            int k = c4 * 4 + u;
            As[k * GA_STR + 2 * rowA]            = pa0[u];
            As[k * GA_STR + 2 * rowA + 1]        = pa0[u];
            As[k * GA_STR + 2 * (rowA + 64)]     = pa1[u];
            As[k * GA_STR + 2 * (rowA + 64) + 1] = pa1[u];
            Bs[k * 132 + rowA]                   = pb0[u];
            Bs[k * 132 + rowA + 64]              = pb1[u];
        }
    }
    __syncthreads();

#pragma unroll 1
    for (int s = 0; s < 16; s++) {
        const int buf = s & 1;
        if (s < 15) {
            int ks = (s + 1) * 16;
            ra[0] = *(const float4*)(Ag + (size_t)rowA * CD + ks + c4 * 4);
            ra[1] = *(const float4*)(Ag + (size_t)(rowA + 64) * CD + ks + c4 * 4);
            rb[0] = *(const float4*)(Bg + (size_t)rowA * CD + ks + c4 * 4);
            rb[1] = *(const float4*)(Bg + (size_t)(rowA + 64) * CD + ks + c4 * 4);
        }
        const float* Ab = As + buf * GA_BUF;
        const float* Bb = Bs + buf * GB_BUF;
#pragma unroll
        for (int kk = 0; kk < 16; kk++) {
            u64 av[8], bv[4];
#pragma unroll
            for (int i = 0; i < 8; i++)
                av[i] = *(const u64*)&Ab[kk * GA_STR + 2 * (ty * 8 + i)];
#pragma unroll
            for (int j = 0; j < 4; j++)
                bv[j] = *(const u64*)&Bb[kk * 132 + 2 * tx + 32 * j];
#pragma unroll
            for (int i = 0; i < 8; i++)
#pragma unroll
                for (int j = 0; j < 4; j++) ffma2(acc[i][j], av[i], bv[j]);
        }
        if (s < 15) {
            const int nbuf = buf ^ 1;
            float* An = As + nbuf * GA_BUF;
            float* Bn = Bs + nbuf * GB_BUF;
            const float* pa0 = (const float*)&ra[0];
            const float* pa1 = (const float*)&ra[1];
            const float* pb0 = (const float*)&rb[0];
            const float* pb1 = (const float*)&rb[1];
#pragma unroll
            for (int u = 0; u < 4; u++) {
                int k = c4 * 4 + u;
                An[k * GA_STR + 2 * rowA]            = pa0[u];
                An[k * GA_STR + 2 * rowA + 1]        = pa0[u];
                An[k * GA_STR + 2 * (rowA + 64)]     = pa1[u];
                An[k * GA_STR + 2 * (rowA + 64) + 1] = pa1[u];
                Bn[k * 132 + rowA]                   = pb0[u];
                Bn[k * 132 + rowA + 64]              = pb1[u];
            }
            __syncthreads();
        }
    }

    // epilogue: contiguous p-major store; bias only for v half
    const int isv   = (n0 >= 256);
    const int cbase = n0 & 255;
    float* dst = isv ? g_v : g_z;
#pragma unroll
    for (int i = 0; i < 8; i++) {
        int p = m0 + ty * 8 + i;
        size_t base = (size_t)p * CD + cbase;
#pragma unroll
        for (int j = 0; j < 4; j++) {
            int col = 2 * tx + 32 * j;
            float2 r = unpack2(acc[i][j]);
            if (isv) {
                float2 bv2 = *(const float2*)(bias + 512 + cbase + col);
                r.x += bv2.x; r.y += bv2.y;
            }
            *(float2*)(dst + base + col) = r;
        }
    }
}

// ============================================================================
// Kernel 1b: column corrections.
// ============================================================================
__global__ __launch_bounds__(256) void corr_kernel(const float* __restrict__ X)
{
    __shared__ float red[256];
    const int id = blockIdx.x;          // 0..1535
    const int which = id / 768;
    const int r = id - which * 768;
    const int b = r / 96, idx = r - b * 96;
    const int c = threadIdx.x;

    const float uv = which ? g_u[c] : g_u2[c];
    size_t base; int stride;
    if (which == 0) { base = (size_t)b * BOFF + (size_t)idx * 256; stride = 24576; }
    else           { base = (size_t)b * BOFF + (size_t)idx * 24576; stride = 256; }

    float s = 0.f;
#pragma unroll 4
    for (int t = 0; t < 96; t++)
        s += X[base + (size_t)t * stride + c];
    red[c] = s * uv;
    __syncthreads();
#pragma unroll
    for (int o = 128; o; o >>= 1) {
        if (c < o) red[c] += red[c + o];
        __syncthreads();
    }
    if (c == 0) g_corr[which * 768 + r] = red[0];
}

// ============================================================================
// Kernel 2: logit partials, both axes, split-K. grid (NSPLIT, 16).
//  mode0 (ms): S[h,h'] = sum x_{hw}.z_{h'w}  A=x, B=z, rowStride=256,  chunkStride=24576
//  mode1 (ma): S[w,w'] = sum z_{hw}.x_{hw'}  A=z, B=x, rowStride=24576, chunkStride=256
// A duplicated in smem [k][2*row]; B [k][row]. 6x6 microtile via LDS.64 pairs.
// ============================================================================
#define SA_STR 194                /* 2*96 + 2 */
#define SA_BUF (32 * SA_STR)      /* 6208 floats */
#define SB_BUF (32 * 98)          /* 3136 floats */
#define S_SMEM ((2 * SA_BUF + 2 * SB_BUF) * 4)   /* 74752 B */

__global__ __launch_bounds__(256, 3) void s_kernel(const float* __restrict__ X)
{
    extern __shared__ __align__(16) float ssm[];
    float* Asm = ssm;                         // [2][SA_BUF]
    float* Bsm = ssm + 2 * SA_BUF;            // [2][SB_BUF]

    const int split = blockIdx.x;
    const int mb    = blockIdx.y;
    const int mode  = mb >> 3;
    const int b     = mb & 7;

    const float* A = mode ? g_z : X;
    const float* B = mode ? X   : g_z;
    const int rowStride   = mode ? 24576 : 256;
    const int chunkStride = mode ? 256   : 24576;
    const size_t bbase = (size_t)b * BOFF;

    const int tid = threadIdx.x;
    const int tx = tid & 15, ty = tid >> 4;
    const int srow = tid >> 3;    // staging row 0..31 (+32,+64)
    const int q8   = tid & 7;

    u64 acc[6][3];
#pragma unroll
    for (int i = 0; i < 6; i++)
#pragma unroll
        for (int j = 0; j < 3; j++) acc[i][j] = 0ULL;

    float4 ra[3], rbv[3];
    {
        int kg0 = split * KSPLIT + q8 * 4;
        int chunk = kg0 >> 8, cin = kg0 & 255;
#pragma unroll
        for (int r = 0; r < 3; r++) {
            int row = srow + 32 * r;
            size_t ga = bbase + (size_t)row * rowStride + (size_t)chunk * chunkStride + cin;
            ra[r]  = *(const float4*)(A + ga);
            rbv[r] = *(const float4*)(B + ga);
        }
#pragma unroll
        for (int r = 0; r < 3; r++) {
            int row = srow + 32 * r;
            const float* pa = (const float*)&ra[r];
            const float* pb = (const float*)&rbv[r];
#pragma unroll
            for (int u = 0; u < 4; u++) {
                int k = q8 * 4 + u;
                Asm[k * SA_STR + 2 * row]     = pa[u];
                Asm[k * SA_STR + 2 * row + 1] = pa[u];
                Bsm[k * 98 + row]             = pb[u];
            }
        }
    }
    __syncthreads();

#pragma unroll 1
    for (int kb = 0; kb < KSPLIT / 32; kb++) {
        const int buf = kb & 1;
        if (kb < KSPLIT / 32 - 1) {
            int kg0 = split * KSPLIT + (kb + 1) * 32 + q8 * 4;
            int chunk = kg0 >> 8, cin = kg0 & 255;
#pragma unroll
            for (int r = 0; r < 3; r++) {
                int row = srow + 32 * r;
                size_t ga = bbase + (size_t)row * rowStride + (size_t)chunk * chunkStride + cin;
                ra[r]  = *(const float4*)(A + ga);
                rbv[r] = *(const float4*)(B + ga);
            }
        }
        const float* Ab = Asm + buf * SA_BUF;
        const float* Bb = Bsm + buf * SB_BUF;
#pragma unroll 8
        for (int kk = 0; kk < 32; kk++) {
            u64 a[6], bv[3];
#pragma unroll
            for (int i = 0; i < 6; i++)
                a[i] = *(const u64*)&Ab[kk * SA_STR + 2 * (ty * 6 + i)];
#pragma unroll
            for (int j = 0; j < 3; j++)
                bv[j] = *(const u64*)&Bb[kk * 98 + 6 * tx + 2 * j];
#pragma unroll
            for (int i = 0; i < 6; i++)
#pragma unroll
                for (int j = 0; j < 3; j++) ffma2(acc[i][j], a[i], bv[j]);
        }
        if (kb < KSPLIT / 32 - 1) {
            const int nbuf = buf ^ 1;
            float* An = Asm + nbuf * SA_BUF;
            float* Bn = Bsm + nbuf * SB_BUF;
#pragma unroll
            for (int r = 0; r < 3; r++) {
                int row = srow + 32 * r;
                const float* pa = (const float*)&ra[r];
                const float* pb = (const float*)&rbv[r];
#pragma unroll
                for (int u = 0; u < 4; u++) {
                    int k = q8 * 4 + u;
                    An[k * SA_STR + 2 * row]     = pa[u];
                    An[k * SA_STR + 2 * row + 1] = pa[u];
                    Bn[k * 98 + row]             = pb[u];
                }
            }
            __syncthreads();
        }
    }

    float* dst = g_Sp + (size_t)(split * 16 + mb) * PBATCH;
#pragma unroll
    for (int i = 0; i < 6; i++)
#pragma unroll
        for (int j = 0; j < 3; j++) {
            float2 r = unpack2(acc[i][j]);
            *(float2*)(dst + (ty * 6 + i) * 96 + 6 * tx + 2 * j) = r;
        }
}

// ============================================================================
// Kernel 3: softmax rows of 96 (sum NSPLIT partials + column correction).
// ============================================================================
__global__ __launch_bounds__(32) void softmax_kernel()
{
    const int rowid = blockIdx.x;
    const int mb = rowid / 96, i = rowid - mb * 96;
    const int mode = mb >> 3, b = mb & 7;
    const int t = threadIdx.x;
    const float* corr = g_corr + mode * 768 + b * 96;

    float v[3];
#pragma unroll
    for (int u = 0; u < 3; u++) {
        int j = t + 32 * u;
        float s = corr[j];
#pragma unroll
        for (int sp = 0; sp < NSPLIT; sp++)
            s += g_Sp[(size_t)(sp * 16 + mb) * PBATCH + i * 96 + j];
        v[u] = s;
    }
    float mx = fmaxf(v[0], fmaxf(v[1], v[2]));
#pragma unroll
    for (int o = 16; o; o >>= 1) mx = fmaxf(mx, __shfl_xor_sync(0xffffffffu, mx, o));
    float sum = 0.f;
#pragma unroll
    for (int u = 0; u < 3; u++) { v[u] = expf(v[u] - mx); sum += v[u]; }
#pragma unroll
    for (int o = 16; o; o >>= 1) sum += __shfl_xor_sync(0xffffffffu, sum, o);
    float inv = 1.f / sum;
#pragma unroll
    for (int u = 0; u < 3; u++)
        g_P[mb * PBATCH + i * 96 + t + 32 * u] = v[u] * inv;
}

// ============================================================================
// Kernels 4/5: O_tile(96x128) = P(96x96) * V(96x128). grid (768, 2).
// v and out both p-major [b][w][h][c].
// Ps now PANEL-staged (16 k at a time) in dup layout [k][2*row], double-buffered
// with V — removes the serialized 36KB Ps prologue and the dup MOVs.
// ============================================================================
#define PV_PSTR 194               /* 2*96 + 2 */
#define PV_PSZ  (16 * PV_PSTR)    /* 3104 floats per buffer */
#define PV_VS   (16 * 132)        /* 2112 floats per buffer */
#define PV_SMEM ((2 * PV_PSZ + 2 * PV_VS) * 4)   /* 41728 B */

__global__ __launch_bounds__(256, 3) void pv_kernel(float* __restrict__ out, int mode_ma)
{
    extern __shared__ __align__(16) float dsm[];
    float* Ps = dsm;                  // [2][PV_PSZ]
    float* Vs = dsm + 2 * PV_PSZ;     // [2][PV_VS]

    const int s = blockIdx.x;
    const int ct = blockIdx.y;
    const int b = s / 96, idx = s - b * 96;
    const int c0 = ct * 128;

    size_t vbase, outBase; int vStride, outStride, pBase;
    if (mode_ma) {
        vbase   = (size_t)b * BOFF + (size_t)idx * 256;   vStride = 24576;
        outBase = (size_t)b * BOFF + (size_t)idx * 256;   outStride = 24576;
        pBase = (8 + b) * PBATCH;
    } else {
        vbase   = (size_t)b * BOFF + (size_t)idx * 24576; vStride = 256;
        outBase = (size_t)b * BOFF + (size_t)idx * 24576; outStride = 256;
        pBase = b * PBATCH;
    }

    const int tid = threadIdx.x;
    const int tx = tid & 15, ty = tid >> 4;

    // V staging mapping
    const int vrow  = tid >> 5;     // 0..7 (+8)
    const int vcolq = tid & 31;
    // Ps staging mapping: f = tid + 256r -> row = f>>3 (0..95), cp = f&7 (k-pair)
    const int prow = tid >> 3;      // base row for r=0
    const int pcp  = tid & 7;

    // ---- stage panel 0 (Ps + V) into buffer 0 ----
#pragma unroll
    for (int r = 0; r < 3; r++) {
        int row = prow + 32 * r;
        float2 pval = *(const float2*)&g_P[pBase + row * 96 + pcp * 2];
        int k0 = pcp * 2;
        Ps[k0 * PV_PSTR + 2 * row]           = pval.x;
        Ps[k0 * PV_PSTR + 2 * row + 1]       = pval.x;
        Ps[(k0 + 1) * PV_PSTR + 2 * row]     = pval.y;
        Ps[(k0 + 1) * PV_PSTR + 2 * row + 1] = pval.y;
    }
#pragma unroll
    for (int r2 = 0; r2 < 2; r2++) {
        float4 v4 = *(const float4*)(g_v + vbase + (size_t)(vrow + 8 * r2) * vStride + c0 + vcolq * 4);
        *(float4*)&Vs[(vrow + 8 * r2) * 132 + vcolq * 4] = v4;
    }
    __syncthreads();

    u64 acc[6][4];
#pragma unroll
    for (int i = 0; i < 6; i++)
#pragma unroll
        for (int j = 0; j < 4; j++) acc[i][j] = 0ULL;

    float2 ppre[3];
    float4 vr[2];

#pragma unroll 1
    for (int kb = 0; kb < 6; kb++) {
        const int buf = kb & 1;
        if (kb < 5) {   // prefetch next panel (Ps + V) into registers
#pragma unroll
            for (int r = 0; r < 3; r++) {
                int row = prow + 32 * r;
                ppre[r] = *(const float2*)&g_P[pBase + row * 96 + (kb + 1) * 16 + pcp * 2];
            }
#pragma unroll
            for (int r2 = 0; r2 < 2; r2++)
                vr[r2] = *(const float4*)(g_v + vbase +
                    (size_t)((kb + 1) * 16 + vrow + 8 * r2) * vStride + c0 + vcolq * 4);
        }
        const float* Pb = Ps + buf * PV_PSZ;
        const float* Vb = Vs + buf * PV_VS;
#pragma unroll
        for (int kk = 0; kk < 16; kk++) {
            u64 a[6], bv[4];
#pragma unroll
            for (int i = 0; i < 6; i++)
                a[i] = *(const u64*)&Pb[kk * PV_PSTR + 2 * (ty * 6 + i)];
#pragma unroll
            for (int j = 0; j < 4; j++)
                bv[j] = *(const u64*)&Vb[kk * 132 + 2 * tx + 32 * j];
#pragma unroll
            for (int i = 0; i < 6; i++)
#pragma unroll
                for (int j = 0; j < 4; j++) ffma2(acc[i][j], a[i], bv[j]);
        }
        if (kb < 5) {
            const int nbuf = buf ^ 1;
            float* Pn = Ps + nbuf * PV_PSZ;
            float* Vn = Vs + nbuf * PV_VS;
#pragma unroll
            for (int r = 0; r < 3; r++) {
                int row = prow + 32 * r;
                int k0 = pcp * 2;
                Pn[k0 * PV_PSTR + 2 * row]           = ppre[r].x;
                Pn[k0 * PV_PSTR + 2 * row + 1]       = ppre[r].x;
                Pn[(k0 + 1) * PV_PSTR + 2 * row]     = ppre[r].y;
                Pn[(k0 + 1) * PV_PSTR + 2 * row + 1] = ppre[r].y;
            }
#pragma unroll
            for (int r2 = 0; r2 < 2; r2++)
                *(float4*)&Vn[(vrow + 8 * r2) * 132 + vcolq * 4] = vr[r2];
            __syncthreads();
        }
    }

#pragma unroll
    for (int i = 0; i < 6; i++)
#pragma unroll
        for (int j = 0; j < 4; j++) {
            float2 r = unpack2(acc[i][j]);
            size_t addr = outBase + (size_t)(ty * 6 + i) * outStride + c0 + 2 * tx + 32 * j;
            if (mode_ma) {
                *(float2*)(out + addr) = r;
            } else {
                float2 o = *(const float2*)(out + addr);
                o.x += r.x; o.y += r.y;
                *(float2*)(out + addr) = o;
            }
        }
}

// ============================================================================
extern "C" void kernel_launch(void* const* d_in, const int* in_sizes, int n_in,
                              void* d_out, int out_size) {
    const float* x    = (const float*)d_in[0];
    const float* w    = (const float*)d_in[1];
    const float* bias = (const float*)d_in[2];
    float* out = (float*)d_out;

    static int attr_done = 0;
    if (!attr_done) {
        cudaFuncSetAttribute(gemm_kernel, cudaFuncAttributeMaxDynamicSharedMemorySize, G_SMEM);
        cudaFuncSetAttribute(s_kernel,    cudaFuncAttributeMaxDynamicSharedMemorySize, S_SMEM);
        cudaFuncSetAttribute(pv_kernel,   cudaFuncAttributeMaxDynamicSharedMemorySize, PV_SMEM);
        attr_done = 1;
    }

    prep_kernel<<<514, 256>>>(w, bias);
    gemm_kernel<<<dim3(576, 4), 256, G_SMEM>>>(x, bias);
    corr_kernel<<<1536, 256>>>(x);
    s_kernel<<<dim3(NSPLIT, 16), 256, S_SMEM>>>(x);
    softmax_kernel<<<16 * 96, 32>>>();
    pv_kernel<<<dim3(768, 2), 256, PV_SMEM>>>(out, 1);  // ma: full overwrite
    pv_kernel<<<dim3(768, 2), 256, PV_SMEM>>>(out, 0);  // ms: accumulate
}

// round 13
// speedup vs baseline: 1.2046x; 1.1675x over previous
#include <cuda_runtime.h>
#include <cstdint>

typedef unsigned long long u64;

#define NB 8
#define WD 96
#define HD 96
#define CD 256
#define PBATCH (WD*HD)            /* 9216 */
#define BOFF (PBATCH*CD)          /* 2359296 floats per batch */
#define ARRN (NB*BOFF)            /* 18874368 */
#define NSPLIT 48
#define KSPLIT 512

// ---------------- device scratch ----------------
__device__ float g_z[ARRN];                   // z = G x, p-major [b][w][h][c]
__device__ float g_v[ARRN];                   // v, p-major
__device__ float g_Sp[NSPLIT * 16 * PBATCH];  // [split][mode*8+b][96][96]
__device__ float g_P[16 * PBATCH];            // softmaxed probs
__device__ float g_wc[512 * 256];             // [G ; Wv] combined weight
__device__ float g_u[256];                    // Wq^T bk
__device__ float g_u2[256];                   // Wk^T bq
__device__ float g_corr[2 * 768];             // [Cms ; Cma] col corrections

// ---------------- f32x2 helpers ----------------
__device__ __forceinline__ void ffma2(u64 &d, u64 a, u64 b) {
    asm("fma.rn.f32x2 %0, %1, %2, %0;" : "+l"(d) : "l"(a), "l"(b));
}
__device__ __forceinline__ u64 dup2(float x) {
    u64 r; asm("mov.b64 %0, {%1, %1};" : "=l"(r) : "f"(x)); return r;
}
__device__ __forceinline__ float2 unpack2(u64 v) {
    float2 f; asm("mov.b64 {%0, %1}, %2;" : "=f"(f.x), "=f"(f.y) : "l"(v)); return f;
}

// ---------------- tf32 mma helpers ----------------
__device__ __forceinline__ uint32_t tf32cvt(float x) {
    uint32_t u; asm("cvt.rna.tf32.f32 %0, %1;" : "=r"(u) : "f"(x)); return u;
}
__device__ __forceinline__ void mma1688(float* c, const uint32_t* a, const uint32_t* b) {
    asm volatile("mma.sync.aligned.m16n8k8.row.col.f32.tf32.tf32.f32 "
        "{%0,%1,%2,%3}, {%4,%5,%6,%7}, {%8,%9}, {%0,%1,%2,%3};"
        : "+f"(c[0]), "+f"(c[1]), "+f"(c[2]), "+f"(c[3])
        : "r"(a[0]), "r"(a[1]), "r"(a[2]), "r"(a[3]), "r"(b[0]), "r"(b[1]));
}

// ============================================================================
// Kernel 0: prep. Blocks 0..255: G[o][c] = sum_t Wq[t][o]*Wk[t][c].
// Blocks 256..511: copy Wv rows. Block 512: u. Block 513: u2.
// ============================================================================
__global__ __launch_bounds__(256) void prep_kernel(
    const float* __restrict__ W, const float* __restrict__ bias)
{
    const int blk = blockIdx.x;
    const int c = threadIdx.x;
    if (blk < 256) {
        __shared__ float sWq[256];
        sWq[c] = W[c * 256 + blk];          // Wq[t=c][o=blk]
        __syncthreads();
        float acc = 0.f;
#pragma unroll 4
        for (int t = 0; t < 256; t++)
            acc += sWq[t] * W[(256 + t) * 256 + c];   // Wk[t][c]
        g_wc[blk * 256 + c] = acc;          // G[o=blk][c]
    } else if (blk < 512) {
        int o = blk - 256;
        g_wc[(256 + o) * 256 + c] = W[(512 + o) * 256 + c];   // Wv[o][c]
    } else if (blk == 512) {
        float acc = 0.f;
#pragma unroll 4
        for (int t = 0; t < 256; t++)
            acc += W[t * 256 + c] * bias[256 + t];    // Wq[t][c]*bk[t]
        g_u[c] = acc;
    } else {
        float acc = 0.f;
#pragma unroll 4
        for (int t = 0; t < 256; t++)
            acc += W[(256 + t) * 256 + c] * bias[t];  // Wk[t][c]*bq[t]
        g_u2[c] = acc;
    }
}

// ============================================================================
// Kernel 1: main GEMM on tensor cores (tf32 mma.sync, 2-way hi/lo split).
// Y[p][o] = sum_c X[p][c]*Wcomb[o][c]; Y = Xhi*Whi + Xhi*Wlo + Xlo*Whi.
// CTA tile 128x64, K panels of 16 (2 k8-steps), double-buffered smem.
// 8 warps: wm=wid&3 (32 rows), wn=wid>>2 (32 cols); warp = 2x4 m16n8 tiles.
// smem [row][20]: all fragment scalar LDS are 1-wavefront (proven bank map).
// ============================================================================
#define GT_STR 20
#define GT_A   (128 * GT_STR)          /* 2560 u32 per A array */
#define GT_B   (64 * GT_STR)           /* 1280 u32 per B array */
#define GT_BUF (2 * GT_A + 2 * GT_B)   /* Ahi,Alo,Bhi,Blo = 7680 */
#define GT_SMEM (2 * GT_BUF * 4)       /* 61440 B */

__global__ __launch_bounds__(256, 2) void gemm_kernel(
    const float* __restrict__ X, const float* __restrict__ bias)
{
    extern __shared__ __align__(16) uint32_t gts[];
    uint32_t* Ahi = gts;                       // [2][GT_A]
    uint32_t* Alo = gts + 2 * GT_A;
    uint32_t* Bhi = gts + 4 * GT_A;            // [2][GT_B]
    uint32_t* Blo = gts + 4 * GT_A + 2 * GT_B;

    const int tid  = threadIdx.x;
    const int lane = tid & 31, wid = tid >> 5;
    const int wm = wid & 3, wn = wid >> 2;
    const int m0 = blockIdx.x * 128;
    const int n0 = blockIdx.y * 64;

    const float* Ag = X    + (size_t)m0 * CD;
    const float* Bg = g_wc + (size_t)n0 * CD;

    const int srow = tid >> 2;     // staging row (A: +64 second it; B: 0..63)
    const int c4   = tid & 3;

    float acc[2][4][4];
#pragma unroll
    for (int tm = 0; tm < 2; tm++)
#pragma unroll
        for (int tn = 0; tn < 4; tn++)
#pragma unroll
            for (int q = 0; q < 4; q++) acc[tm][tn][q] = 0.f;

    // ---- stage panel 0 ----
    float4 ra[2], rb;
    ra[0] = *(const float4*)(Ag + (size_t)srow * CD + c4 * 4);
    ra[1] = *(const float4*)(Ag + (size_t)(srow + 64) * CD + c4 * 4);
    rb    = *(const float4*)(Bg + (size_t)srow * CD + c4 * 4);
    {
#pragma unroll
        for (int it = 0; it < 2; it++) {
            const float* pa = (const float*)&ra[it];
            uint4 h, l;
            uint32_t* hp = (uint32_t*)&h; uint32_t* lp = (uint32_t*)&l;
#pragma unroll
            for (int u = 0; u < 4; u++) {
                uint32_t hb = tf32cvt(pa[u]);
                hp[u] = hb;
                lp[u] = tf32cvt(pa[u] - __uint_as_float(hb));
            }
            int off = (srow + 64 * it) * GT_STR + c4 * 4;
            *(uint4*)&Ahi[off] = h;
            *(uint4*)&Alo[off] = l;
        }
        const float* pb = (const float*)&rb;
        uint4 h, l;
        uint32_t* hp = (uint32_t*)&h; uint32_t* lp = (uint32_t*)&l;
#pragma unroll
        for (int u = 0; u < 4; u++) {
            uint32_t hb = tf32cvt(pb[u]);
            hp[u] = hb;
            lp[u] = tf32cvt(pb[u] - __uint_as_float(hb));
        }
        int off = srow * GT_STR + c4 * 4;
        *(uint4*)&Bhi[off] = h;
        *(uint4*)&Blo[off] = l;
    }
    __syncthreads();

#pragma unroll 1
    for (int s = 0; s < 16; s++) {
        const int buf = s & 1;
        if (s < 15) {
            int ks = (s + 1) * 16;
            ra[0] = *(const float4*)(Ag + (size_t)srow * CD + ks + c4 * 4);
            ra[1] = *(const float4*)(Ag + (size_t)(srow + 64) * CD + ks + c4 * 4);
            rb    = *(const float4*)(Bg + (size_t)srow * CD + ks + c4 * 4);
        }
        const uint32_t* Abh = Ahi + buf * GT_A;
        const uint32_t* Abl = Alo + buf * GT_A;
        const uint32_t* Bbh = Bhi + buf * GT_B;
        const uint32_t* Bbl = Blo + buf * GT_B;
#pragma unroll
        for (int g = 0; g < 2; g++) {
            uint32_t ah[2][4], al[2][4];
#pragma unroll
            for (int tm = 0; tm < 2; tm++)
#pragma unroll
                for (int q = 0; q < 4; q++) {
                    int r = 32 * wm + 16 * tm + (lane >> 2) + 8 * (q & 1);
                    int c = 8 * g + (lane & 3) + 4 * (q >> 1);
                    ah[tm][q] = Abh[r * GT_STR + c];
                    al[tm][q] = Abl[r * GT_STR + c];
                }
            uint32_t bh[4][2], bl[4][2];
#pragma unroll
            for (int tn = 0; tn < 4; tn++)
#pragma unroll
                for (int q = 0; q < 2; q++) {
                    int n = 32 * wn + 8 * tn + (lane >> 2);
                    int k = 8 * g + (lane & 3) + 4 * q;
                    bh[tn][q] = Bbh[n * GT_STR + k];
                    bl[tn][q] = Bbl[n * GT_STR + k];
                }
#pragma unroll
            for (int tm = 0; tm < 2; tm++)
#pragma unroll
                for (int tn = 0; tn < 4; tn++) {
                    mma1688(acc[tm][tn], ah[tm], bh[tn]);
                    mma1688(acc[tm][tn], ah[tm], bl[tn]);
                    mma1688(acc[tm][tn], al[tm], bh[tn]);
                }
        }
        if (s < 15) {
            const int nbuf = buf ^ 1;
            uint32_t* Anh = Ahi + nbuf * GT_A;
            uint32_t* Anl = Alo + nbuf * GT_A;
            uint32_t* Bnh = Bhi + nbuf * GT_B;
            uint32_t* Bnl = Blo + nbuf * GT_B;
#pragma unroll
            for (int it = 0; it < 2; it++) {
                const float* pa = (const float*)&ra[it];
                uint4 h, l;
                uint32_t* hp = (uint32_t*)&h; uint32_t* lp = (uint32_t*)&l;
#pragma unroll
                for (int u = 0; u < 4; u++) {
                    uint32_t hb = tf32cvt(pa[u]);
                    hp[u] = hb;
                    lp[u] = tf32cvt(pa[u] - __uint_as_float(hb));
                }
                int off = (srow + 64 * it) * GT_STR + c4 * 4;
                *(uint4*)&Anh[off] = h;
                *(uint4*)&Anl[off] = l;
            }
            const float* pb = (const float*)&rb;
            uint4 h, l;
            uint32_t* hp = (uint32_t*)&h; uint32_t* lp = (uint32_t*)&l;
#pragma unroll
            for (int u = 0; u < 4; u++) {
                uint32_t hb = tf32cvt(pb[u]);
                hp[u] = hb;
                lp[u] = tf32cvt(pb[u] - __uint_as_float(hb));
            }
            int off = srow * GT_STR + c4 * 4;
            *(uint4*)&Bnh[off] = h;
            *(uint4*)&Bnl[off] = l;
            __syncthreads();
        }
    }

    // epilogue: p-major store; bias only for v half
    const int isv   = (n0 >= 256);
    const int cbase = n0 & 255;
    float* dst = isv ? g_v : g_z;
#pragma unroll
    for (int tm = 0; tm < 2; tm++)
#pragma unroll
        for (int tn = 0; tn < 4; tn++)
#pragma unroll
            for (int half = 0; half < 2; half++) {
                int p  = m0 + 32 * wm + 16 * tm + (lane >> 2) + 8 * half;
                int cl = cbase + 32 * wn + 8 * tn + 2 * (lane & 3);
                float2 r = make_float2(acc[tm][tn][2 * half], acc[tm][tn][2 * half + 1]);
                if (isv) {
                    float2 bv = *(const float2*)(bias + 512 + cl);
                    r.x += bv.x; r.y += bv.y;
                }
                *(float2*)(dst + (size_t)p * CD + cl) = r;
            }
}

// ============================================================================
// Kernel 1b: column corrections.
// ============================================================================
__global__ __launch_bounds__(256) void corr_kernel(const float* __restrict__ X)
{
    __shared__ float red[256];
    const int id = blockIdx.x;          // 0..1535
    const int which = id / 768;
    const int r = id - which * 768;
    const int b = r / 96, idx = r - b * 96;
    const int c = threadIdx.x;

    const float uv = which ? g_u[c] : g_u2[c];
    size_t base; int stride;
    if (which == 0) { base = (size_t)b * BOFF + (size_t)idx * 256; stride = 24576; }
    else           { base = (size_t)b * BOFF + (size_t)idx * 24576; stride = 256; }

    float s = 0.f;
#pragma unroll 4
    for (int t = 0; t < 96; t++)
        s += X[base + (size_t)t * stride + c];
    red[c] = s * uv;
    __syncthreads();
#pragma unroll
    for (int o = 128; o; o >>= 1) {
        if (c < o) red[c] += red[c + o];
        __syncthreads();
    }
    if (c == 0) g_corr[which * 768 + r] = red[0];
}

// ============================================================================
// Kernel 2: logit partials (exact 826us version). grid (NSPLIT, 16).
// ============================================================================
__global__ __launch_bounds__(256, 3) void s_kernel(const float* __restrict__ X)
{
    __shared__ __align__(16) float As[32 * 98];
    __shared__ __align__(16) float Bs[32 * 98];

    const int split = blockIdx.x;
    const int mb    = blockIdx.y;
    const int mode  = mb >> 3;
    const int b     = mb & 7;

    const float* A = mode ? g_z : X;
    const float* B = mode ? X   : g_z;
    const int rowStride   = mode ? 24576 : 256;
    const int chunkStride = mode ? 256   : 24576;
    const size_t bbase = (size_t)b * BOFF;

    const int tid = threadIdx.x;
    const int tx = tid & 15, ty = tid >> 4;

    u64 acc[6][3];
#pragma unroll
    for (int i = 0; i < 6; i++)
#pragma unroll
        for (int j = 0; j < 3; j++) acc[i][j] = 0ULL;

#pragma unroll 1
    for (int kb = 0; kb < KSPLIT / 32; kb++) {
#pragma unroll
        for (int r = 0; r < 3; r++) {
            int f   = tid + 256 * r;
            int row = f >> 3;
            int k4  = f & 7;
            int kg0 = split * KSPLIT + kb * 32 + k4 * 4;
            int chunk = kg0 >> 8, cin = kg0 & 255;
            size_t ga = bbase + (size_t)row * rowStride + (size_t)chunk * chunkStride + cin;
            float4 a4 = *(const float4*)(A + ga);
            float4 b4 = *(const float4*)(B + ga);
            int ks = k4 * 4;
            As[(ks+0)*98 + row] = a4.x; As[(ks+1)*98 + row] = a4.y;
            As[(ks+2)*98 + row] = a4.z; As[(ks+3)*98 + row] = a4.w;
            Bs[(ks+0)*98 + row] = b4.x; Bs[(ks+1)*98 + row] = b4.y;
            Bs[(ks+2)*98 + row] = b4.z; Bs[(ks+3)*98 + row] = b4.w;
        }
        __syncthreads();
#pragma unroll 8
        for (int kk = 0; kk < 32; kk++) {
            u64 a[6], bv[3];
#pragma unroll
            for (int i = 0; i < 6; i++) a[i] = dup2(As[kk * 98 + ty * 6 + i]);
#pragma unroll
            for (int j = 0; j < 3; j++) bv[j] = *(const u64*)&Bs[kk * 98 + 6 * tx + 2 * j];
#pragma unroll
            for (int i = 0; i < 6; i++)
#pragma unroll
                for (int j = 0; j < 3; j++) ffma2(acc[i][j], a[i], bv[j]);
        }
        __syncthreads();
    }

    float* dst = g_Sp + (size_t)(split * 16 + mb) * PBATCH;
#pragma unroll
    for (int i = 0; i < 6; i++)
#pragma unroll
        for (int j = 0; j < 3; j++) {
            float2 r = unpack2(acc[i][j]);
            *(float2*)(dst + (ty * 6 + i) * 96 + 6 * tx + 2 * j) = r;
        }
}

// ============================================================================
// Kernel 3: softmax rows of 96 (sum NSPLIT partials + column correction).
// ============================================================================
__global__ __launch_bounds__(32) void softmax_kernel()
{
    const int rowid = blockIdx.x;
    const int mb = rowid / 96, i = rowid - mb * 96;
    const int mode = mb >> 3, b = mb & 7;
    const int t = threadIdx.x;
    const float* corr = g_corr + mode * 768 + b * 96;

    float v[3];
#pragma unroll
    for (int u = 0; u < 3; u++) {
        int j = t + 32 * u;
        float s = corr[j];
#pragma unroll
        for (int sp = 0; sp < NSPLIT; sp++)
            s += g_Sp[(size_t)(sp * 16 + mb) * PBATCH + i * 96 + j];
        v[u] = s;
    }
    float mx = fmaxf(v[0], fmaxf(v[1], v[2]));
#pragma unroll
    for (int o = 16; o; o >>= 1) mx = fmaxf(mx, __shfl_xor_sync(0xffffffffu, mx, o));
    float sum = 0.f;
#pragma unroll
    for (int u = 0; u < 3; u++) { v[u] = expf(v[u] - mx); sum += v[u]; }
#pragma unroll
    for (int o = 16; o; o >>= 1) sum += __shfl_xor_sync(0xffffffffu, sum, o);
    float inv = 1.f / sum;
#pragma unroll
    for (int u = 0; u < 3; u++)
        g_P[mb * PBATCH + i * 96 + t + 32 * u] = v[u] * inv;
}

// ============================================================================
// Kernels 4/5: O_tile(96x128) = P(96x96) * V(96x128). grid (768, 2).
// (exact 826us version)
// ============================================================================
#define PV_PS   (96 * 97)
#define PV_VS   (16 * 132)
#define PV_SMEM ((PV_PS + 2 * PV_VS) * 4)

__global__ __launch_bounds__(256, 3) void pv_kernel(float* __restrict__ out, int mode_ma)
{
    extern __shared__ __align__(16) float dsm[];
    float* Ps = dsm;
    float* Vs = dsm + PV_PS;

    const int s = blockIdx.x;
    const int ct = blockIdx.y;
    const int b = s / 96, idx = s - b * 96;
    const int c0 = ct * 128;

    size_t vbase, outBase; int vStride, outStride, pBase;
    if (mode_ma) {
        vbase   = (size_t)b * BOFF + (size_t)idx * 256;   vStride = 24576;
        outBase = (size_t)b * BOFF + (size_t)idx * 256;   outStride = 24576;
        pBase = (8 + b) * PBATCH;
    } else {
        vbase   = (size_t)b * BOFF + (size_t)idx * 24576; vStride = 256;
        outBase = (size_t)b * BOFF + (size_t)idx * 24576; outStride = 256;
        pBase = b * PBATCH;
    }

    const int tid = threadIdx.x;
    const int tx = tid & 15, ty = tid >> 4;

    for (int f = tid; f < 96 * 96; f += 256) {
        int r = f / 96, k = f - r * 96;
        Ps[r * 97 + k] = g_P[pBase + f];
    }

    const int vrow  = tid >> 5;
    const int vcolq = tid & 31;
    float4 vr[2];
#pragma unroll
    for (int r2 = 0; r2 < 2; r2++)
        vr[r2] = *(const float4*)(g_v + vbase + (size_t)(vrow + 8 * r2) * vStride + c0 + vcolq * 4);
#pragma unroll
    for (int r2 = 0; r2 < 2; r2++)
        *(float4*)&Vs[(vrow + 8 * r2) * 132 + vcolq * 4] = vr[r2];
    __syncthreads();

    u64 acc[6][4];
#pragma unroll
    for (int i = 0; i < 6; i++)
#pragma unroll
        for (int j = 0; j < 4; j++) acc[i][j] = 0ULL;

#pragma unroll 1
    for (int kb = 0; kb < 6; kb++) {
        const int buf = kb & 1;
        if (kb < 5) {
#pragma unroll
            for (int r2 = 0; r2 < 2; r2++)
                vr[r2] = *(const float4*)(g_v + vbase +
                    (size_t)((kb + 1) * 16 + vrow + 8 * r2) * vStride + c0 + vcolq * 4);
        }
        const float* Vb = Vs + buf * PV_VS;
#pragma unroll
        for (int kk = 0; kk < 16; kk++) {
            int kg = kb * 16 + kk;
            u64 a[6], bv[4];
#pragma unroll
            for (int i = 0; i < 6; i++) a[i] = dup2(Ps[(ty * 6 + i) * 97 + kg]);
#pragma unroll
            for (int j = 0; j < 4; j++) bv[j] = *(const u64*)&Vb[kk * 132 + 2 * tx + 32 * j];
#pragma unroll
            for (int i = 0; i < 6; i++)
#pragma unroll
                for (int j = 0; j < 4; j++) ffma2(acc[i][j], a[i], bv[j]);
        }
        if (kb < 5) {
            float* Vn = Vs + (buf ^ 1) * PV_VS;
#pragma unroll
            for (int r2 = 0; r2 < 2; r2++)
                *(float4*)&Vn[(vrow + 8 * r2) * 132 + vcolq * 4] = vr[r2];
            __syncthreads();
        }
    }

#pragma unroll
    for (int i = 0; i < 6; i++)
#pragma unroll
        for (int j = 0; j < 4; j++) {
            float2 r = unpack2(acc[i][j]);
            size_t addr = outBase + (size_t)(ty * 6 + i) * outStride + c0 + 2 * tx + 32 * j;
            if (mode_ma) {
                *(float2*)(out + addr) = r;
            } else {
                float2 o = *(const float2*)(out + addr);
                o.x += r.x; o.y += r.y;
                *(float2*)(out + addr) = o;
            }
        }
}

// ============================================================================
extern "C" void kernel_launch(void* const* d_in, const int* in_sizes, int n_in,
                              void* d_out, int out_size) {
    const float* x    = (const float*)d_in[0];
    const float* w    = (const float*)d_in[1];
    const float* bias = (const float*)d_in[2];
    float* out = (float*)d_out;

    static int attr_done = 0;
    if (!attr_done) {
        cudaFuncSetAttribute(gemm_kernel, cudaFuncAttributeMaxDynamicSharedMemorySize, GT_SMEM);
        cudaFuncSetAttribute(pv_kernel,   cudaFuncAttributeMaxDynamicSharedMemorySize, PV_SMEM);
        attr_done = 1;
    }

    prep_kernel<<<514, 256>>>(w, bias);
    gemm_kernel<<<dim3(576, 8), 256, GT_SMEM>>>(x, bias);
    corr_kernel<<<1536, 256>>>(x);
    s_kernel<<<dim3(NSPLIT, 16), 256>>>(x);
    softmax_kernel<<<16 * 96, 32>>>();
    pv_kernel<<<dim3(768, 2), 256, PV_SMEM>>>(out, 1);  // ma: full overwrite
    pv_kernel<<<dim3(768, 2), 256, PV_SMEM>>>(out, 0);  // ms: accumulate
}